// round 9
// baseline (speedup 1.0000x reference)
#include <cuda_runtime.h>
#include <cstdint>

// Problem constants
#define Bx 8
#define Cc 128
#define Hh 128
#define Ww 128
#define KWIN 9
#define PWPAD 4
#define Tt 128   // conv (row) dimension
#define Ss 128   // scan dimension

// Block decomposition: 128 blocks = 8 batches x (2 T-halves x 8 co-tiles of 16)
#define THALF 64
#define WIN_ROWS (THALF + 2*PWPAD)       // 72
#define NTHR 512

// smem layout (all sizes in floats)
#define CP 132                            // s_prev pitch
#define SPREV_FLOATS (WIN_ROWS * CP)      // 9504
#define WPITCH 18                         // s_wt per-(k,ci) pitch: conflict-free LDS.64
#define SWT_FLOATS (KWIN * Cc * WPITCH)   // 20736
#define REDP 34                           // per-writer pitch (32 floats + 2 pad)
#define SRED_FLOATS (NTHR * REDP)         // 17408
#define SMEM_BYTES ((SPREV_FLOATS + SWT_FLOATS + SRED_FLOATS) * 4)  // 190592 B

// Scratch tensors (B, S, T, C)
__device__ float g_buf0[(size_t)Bx*Ss*Tt*Cc];
__device__ float g_buf1[(size_t)Bx*Ss*Tt*Cc];
// Per-batch sync counters (one set per scan kernel)
__device__ int g_cnt0[Bx];
__device__ int g_cnt1[Bx];

// ---------------------------------------------------------------------------
__global__ void reset_kernel(int* c0, int* c1) {
    if (threadIdx.x < Bx) { c0[threadIdx.x] = 0; c1[threadIdx.x] = 0; }
}

// transpose_in: x (B,C,H,W) -> buf (B,H,W,C)
__global__ void transpose_in_kernel(const float* __restrict__ x, float* __restrict__ out) {
    __shared__ float tile[32][33];
    int w0 = blockIdx.x * 32, c0 = blockIdx.y * 32;
    int bh = blockIdx.z;
    int b = bh >> 7, h = bh & 127;
#pragma unroll
    for (int j = 0; j < 32; j += 8) {
        int c = c0 + threadIdx.y + j;
        tile[threadIdx.y + j][threadIdx.x] =
            x[((size_t)(b * Cc + c) * Hh + h) * Ww + w0 + threadIdx.x];
    }
    __syncthreads();
#pragma unroll
    for (int j = 0; j < 32; j += 8) {
        int w = w0 + threadIdx.y + j;
        out[((size_t)(b * Hh + h) * Ww + w) * Cc + c0 + threadIdx.x] =
            tile[threadIdx.x][threadIdx.y + j];
    }
}

// transpose_mid: (B,S,T,C) -> (B,T,S,C)
__global__ void transpose_mid_kernel(const float* __restrict__ in, float* __restrict__ out) {
    int bs = blockIdx.x;
    int b = bs >> 7, s = bs & 127;
    int tid = threadIdx.x;
    int toff = tid >> 5;
    int c4 = (tid & 31) * 4;
    for (int tb = 0; tb < Tt; tb += 4) {
        int t = tb + toff;
        float4 v = *(const float4*)(in + ((size_t)((b * Ss + s) * Tt + t)) * Cc + c4);
        *(float4*)(out + ((size_t)((b * Tt + t) * Ss + s)) * Cc + c4) = v;
    }
}

// transpose_out: buf1 (B, W, H, C) -> out (B, C, H, W)
__global__ void transpose_out_kernel(const float* __restrict__ in, float* __restrict__ out) {
    __shared__ float tile[32][33];
    int w0 = blockIdx.x * 32, c0 = blockIdx.y * 32;
    int bh = blockIdx.z;
    int b = bh >> 7, h = bh & 127;
#pragma unroll
    for (int j = 0; j < 32; j += 8) {
        int w = w0 + threadIdx.y + j;
        tile[threadIdx.y + j][threadIdx.x] =
            in[((size_t)(b * Ww + w) * Hh + h) * Cc + c0 + threadIdx.x];
    }
    __syncthreads();
#pragma unroll
    for (int j = 0; j < 32; j += 8) {
        int c = c0 + threadIdx.y + j;
        out[((size_t)(b * Cc + c) * Hh + h) * Ww + w0 + threadIdx.x] =
            tile[threadIdx.x][threadIdx.y + j];
    }
}

// ---------------------------------------------------------------------------
// One scan step for this block's (T-half, 16-co tile):
//   crow[t, co] += relu( sum_{k,ci} prow[t+k-4, ci] * W[k, ci, co] )
// Thread decomposition (512): tid = tg(8)*64 + ch(4)*16 + cg(16)
//   each thread: 8 t (tg*8+j) x 4 co (ch*4 + 2 pairs), 16-way ci split (cg)
__device__ __forceinline__ void scan_step(
    float* __restrict__ s_prev, const float* __restrict__ s_wt, float* __restrict__ s_red,
    const float* __restrict__ prow, float* __restrict__ crow,
    int t0g, int co0, int* cnt_g, int wait_target, int tid)
{
    // -- x prefetch (this block's slice of crow is stable at step start) --
    const int cp2   = tid & 7;        // co-pair index within 16-co tile
    const int t_out = tid >> 3;       // 0..63 local t this thread outputs
    float* outp = crow + (size_t)(t0g + t_out) * Cc + co0 + cp2 * 2;
    float2 xv = *(const float2*)outp;

    // -- warp-level spin: wait for peer blocks of this batch --
    if ((tid & 31) == 0) {
        int v;
        do {
            asm volatile("ld.acquire.gpu.global.s32 %0, [%1];" : "=r"(v) : "l"(cnt_g));
        } while (v < wait_target);
    }
    __syncwarp();

    // -- fill s_prev window: 72 rows x 128 ch, zero-padded outside [0, Tt) --
    for (int idx = tid; idx < WIN_ROWS * 32; idx += NTHR) {
        int chunk = idx & 31;
        int row   = idx >> 5;
        int tgl = t0g + row - PWPAD;
        float4 v = make_float4(0.f, 0.f, 0.f, 0.f);
        if (tgl >= 0 && tgl < Tt) v = __ldcg((const float4*)(prow + tgl * Cc + chunk * 4));
        *(float4*)(s_prev + row * CP + chunk * 4) = v;
    }
    __syncthreads();

    // -- compute --
    const int cg = tid & 15;
    const int ch = (tid >> 4) & 3;
    const int tg = tid >> 6;
    const int tl0 = tg * 8;

    unsigned long long acc[8][2];
#pragma unroll
    for (int j = 0; j < 8; ++j) { acc[j][0] = 0ull; acc[j][1] = 0ull; }

    for (int i = 0; i < 8; ++i) {
        const int ci = cg + 16 * i;
        unsigned long long a2[16];
#pragma unroll
        for (int j = 0; j < 16; ++j) {
            unsigned u = __float_as_uint(s_prev[(tl0 + j) * CP + ci]);
            asm("mov.b64 %0, {%1, %1};" : "=l"(a2[j]) : "r"(u));
        }
#pragma unroll
        for (int k = 0; k < KWIN; ++k) {
            const float* wr = &s_wt[(k * Cc + ci) * WPITCH + ch * 4];
#pragma unroll
            for (int cp = 0; cp < 2; ++cp) {
                unsigned long long w2 = *(const unsigned long long*)(wr + 2 * cp);
#pragma unroll
                for (int j = 0; j < 8; ++j) {
                    asm("fma.rn.f32x2 %0, %1, %2, %0;"
                        : "+l"(acc[j][cp]) : "l"(a2[j + k]), "l"(w2));
                }
            }
        }
    }

    // -- stash partials (16 u64 per thread; s_red separate region, no pre-barrier) --
    float* myred = s_red + tid * REDP;
#pragma unroll
    for (int j = 0; j < 8; ++j) {
        *(unsigned long long*)(myred + (j * 2 + 0) * 2) = acc[j][0];
        *(unsigned long long*)(myred + (j * 2 + 1) * 2) = acc[j][1];
    }
    __syncthreads();

    // -- 16-way reduce + relu + add x + store --
    // partial for (t_out, co-pair cp2) lives at writer tid_w = (t_out>>3)*64 + (cp2>>1)*16 + g,
    // value offset = ((t_out&7)*2 + (cp2&1))*2
    {
        const float* pr = s_red + ((t_out >> 3) * 64 + (cp2 >> 1) * 16) * REDP
                        + ((t_out & 7) * 2 + (cp2 & 1)) * 2;
        float sx = 0.f, sy = 0.f;
#pragma unroll
        for (int g = 0; g < 16; ++g) {
            float2 p = *(const float2*)(pr + g * REDP);
            sx += p.x; sy += p.y;
        }
        float2 o;
        o.x = xv.x + fmaxf(sx, 0.f);
        o.y = xv.y + fmaxf(sy, 0.f);
        *(float2*)outp = o;
    }

    __syncthreads();
    // release-increment publishes this CTA's stores to the acquire-pollers
    if (tid == 0) {
        asm volatile("red.release.gpu.global.add.s32 [%0], 1;" :: "l"(cnt_g) : "memory");
    }
}

// Persistent kernel: forward scan with Kf, then backward scan with Kb (in-place).
__global__ void __launch_bounds__(NTHR, 1) scan_pair_kernel(
    const float* __restrict__ Kf, const float* __restrict__ Kb,
    float* __restrict__ buf, int* cnt)
{
    extern __shared__ float sm[];
    float* s_prev = sm;
    float* s_wt   = sm + SPREV_FLOATS;
    float* s_red  = sm + SPREV_FLOATS + SWT_FLOATS;

    const int tid   = threadIdx.x;
    const int blk   = blockIdx.x;
    const int b     = blk >> 4;
    const int slice = blk & 15;
    const int t0g   = (slice & 1) * THALF;
    const int co0   = (slice >> 1) * 16;

    float* bbase = buf + (size_t)b * Ss * Tt * Cc;
    int* cnt_g = cnt + b;

    // load forward weights once: s_wt[(k*Cc+ci)*WPITCH + c] = Kf[(k*Cc+ci)*Cc + co0 + c]
    for (int idx = tid; idx < KWIN * Cc * 16; idx += NTHR) {
        int kc = idx >> 4, c = idx & 15;
        s_wt[kc * WPITCH + c] = Kf[(size_t)kc * Cc + co0 + c];
    }
    __syncthreads();

    // forward scan: s = 1..127, prev = s-1
    for (int s = 1; s < Ss; ++s) {
        scan_step(s_prev, s_wt, s_red,
                  bbase + (size_t)(s - 1) * Tt * Cc,
                  bbase + (size_t)s * Tt * Cc,
                  t0g, co0, cnt_g, 16 * (s - 1), tid);
    }

    // switch to backward weights (smem private to block; peers may lag safely)
    __syncthreads();
    for (int idx = tid; idx < KWIN * Cc * 16; idx += NTHR) {
        int kc = idx >> 4, c = idx & 15;
        s_wt[kc * WPITCH + c] = Kb[(size_t)kc * Cc + co0 + c];
    }
    __syncthreads();

    // backward scan: d = 1..127, cur = 127-d, prev = 128-d
    for (int d = 1; d < Ss; ++d) {
        scan_step(s_prev, s_wt, s_red,
                  bbase + (size_t)(Ss - d) * Tt * Cc,
                  bbase + (size_t)(Ss - 1 - d) * Tt * Cc,
                  t0g, co0, cnt_g, 16 * (126 + d), tid);
    }
}

// ---------------------------------------------------------------------------
extern "C" void kernel_launch(void* const* d_in, const int* in_sizes, int n_in,
                              void* d_out, int out_size) {
    const float* x    = (const float*)d_in[0];
    const float* k_td = (const float*)d_in[1];
    const float* k_dt = (const float*)d_in[2];
    const float* k_lr = (const float*)d_in[3];
    const float* k_rl = (const float*)d_in[4];
    float* out = (float*)d_out;

    float *b0, *b1;
    int *c0, *c1;
    cudaGetSymbolAddress((void**)&b0, g_buf0);
    cudaGetSymbolAddress((void**)&b1, g_buf1);
    cudaGetSymbolAddress((void**)&c0, g_cnt0);
    cudaGetSymbolAddress((void**)&c1, g_cnt1);

    cudaFuncSetAttribute(scan_pair_kernel, cudaFuncAttributeMaxDynamicSharedMemorySize, SMEM_BYTES);

    dim3 tgrid(Ww / 32, Cc / 32, Bx * Hh);
    dim3 tblk(32, 8);

    reset_kernel<<<1, 32>>>(c0, c1);

    // (B,C,H,W) -> (B,H,W,C)
    transpose_in_kernel<<<tgrid, tblk>>>(x, b0);

    // vertical scans (td then dt), persistent
    scan_pair_kernel<<<128, NTHR, SMEM_BYTES>>>(k_td, k_dt, b0, c0);

    // (B,H,W,C) -> (B,W,H,C)
    transpose_mid_kernel<<<Bx * Ss, 128>>>(b0, b1);

    // horizontal scans (lr then rl), persistent
    scan_pair_kernel<<<128, NTHR, SMEM_BYTES>>>(k_lr, k_rl, b1, c1);

    // (B,W,H,C) -> (B,C,H,W)
    transpose_out_kernel<<<tgrid, tblk>>>(b1, out);
}

// round 13
// speedup vs baseline: 1.8288x; 1.8288x over previous
#include <cuda_runtime.h>
#include <cstdint>

// Problem constants
#define Bx 8
#define Cc 128
#define Hh 128
#define Ww 128
#define KWIN 9
#define PWPAD 4
#define Tt 128   // conv (row) dimension
#define Ss 128   // scan dimension

// Block decomposition: 128 blocks = 8 batches x (2 T-halves x 8 co-tiles of 16)
#define THALF 64
#define WIN_ROWS (THALF + 2*PWPAD)       // 72
#define FILL_ROWS 68                      // in-range rows per step (4 pad rows static)
#define NTHR 256

// smem layout (floats)
#define CP 130                            // s_prev pitch: 8-row offset = 16 banks -> conflict-free
#define SPREV_FLOATS (WIN_ROWS * CP)      // 9360
#define WPITCH 18                         // s_wt per-(k,ci) pitch: 18*cg distinct mod 32
#define SWT_FLOATS (KWIN * Cc * WPITCH)   // 20736
#define REDP 66                           // stash pitch: 64 floats payload + 2 pad (even, 2cg banks)
#define COPSTRIDE (128 * REDP + 16)       // 8464: +16 banks separates cop halves for reduce
#define SRED_FLOATS (2 * COPSTRIDE)       // 16928
#define SMEM_BYTES ((SPREV_FLOATS + SWT_FLOATS + SRED_FLOATS) * 4)  // 188096 B

// Scratch tensors (B, S, T, C)
__device__ float g_buf0[(size_t)Bx*Ss*Tt*Cc];
__device__ float g_buf1[(size_t)Bx*Ss*Tt*Cc];
// Per-batch sync counters (one set per scan kernel)
__device__ int g_cnt0[Bx];
__device__ int g_cnt1[Bx];

// ---------------------------------------------------------------------------
__global__ void reset_kernel(int* c0, int* c1) {
    if (threadIdx.x < Bx) { c0[threadIdx.x] = 0; c1[threadIdx.x] = 0; }
}

// transpose_in: x (B,C,H,W) -> buf (B,H,W,C)
__global__ void transpose_in_kernel(const float* __restrict__ x, float* __restrict__ out) {
    __shared__ float tile[32][33];
    int w0 = blockIdx.x * 32, c0 = blockIdx.y * 32;
    int bh = blockIdx.z;
    int b = bh >> 7, h = bh & 127;
#pragma unroll
    for (int j = 0; j < 32; j += 8) {
        int c = c0 + threadIdx.y + j;
        tile[threadIdx.y + j][threadIdx.x] =
            x[((size_t)(b * Cc + c) * Hh + h) * Ww + w0 + threadIdx.x];
    }
    __syncthreads();
#pragma unroll
    for (int j = 0; j < 32; j += 8) {
        int w = w0 + threadIdx.y + j;
        out[((size_t)(b * Hh + h) * Ww + w) * Cc + c0 + threadIdx.x] =
            tile[threadIdx.x][threadIdx.y + j];
    }
}

// transpose_mid: (B,S,T,C) -> (B,T,S,C)
__global__ void transpose_mid_kernel(const float* __restrict__ in, float* __restrict__ out) {
    int bs = blockIdx.x;
    int b = bs >> 7, s = bs & 127;
    int tid = threadIdx.x;
    int toff = tid >> 5;
    int c4 = (tid & 31) * 4;
    for (int tb = 0; tb < Tt; tb += 4) {
        int t = tb + toff;
        float4 v = *(const float4*)(in + ((size_t)((b * Ss + s) * Tt + t)) * Cc + c4);
        *(float4*)(out + ((size_t)((b * Tt + t) * Ss + s)) * Cc + c4) = v;
    }
}

// transpose_out: buf1 (B, W, H, C) -> out (B, C, H, W)
__global__ void transpose_out_kernel(const float* __restrict__ in, float* __restrict__ out) {
    __shared__ float tile[32][33];
    int w0 = blockIdx.x * 32, c0 = blockIdx.y * 32;
    int bh = blockIdx.z;
    int b = bh >> 7, h = bh & 127;
#pragma unroll
    for (int j = 0; j < 32; j += 8) {
        int w = w0 + threadIdx.y + j;
        tile[threadIdx.y + j][threadIdx.x] =
            in[((size_t)(b * Ww + w) * Hh + h) * Cc + c0 + threadIdx.x];
    }
    __syncthreads();
#pragma unroll
    for (int j = 0; j < 32; j += 8) {
        int c = c0 + threadIdx.y + j;
        out[((size_t)(b * Cc + c) * Hh + h) * Ww + w0 + threadIdx.x] =
            tile[threadIdx.x][threadIdx.y + j];
    }
}

// ---------------------------------------------------------------------------
// One scan step: crow[t, co] += relu( sum_{k,ci} prow[t+k-4, ci] * W[k, ci, co] )
// Thread decomp (256): tid = cop(2)*128 + tg(8)*16 + cg(16)
//   thread tile: 8 t (tg*8+j) x 8 co (cop*8, 4 pairs), 16-way ci split (cg)
__device__ __forceinline__ void scan_step(
    float* __restrict__ s_prev, const float* __restrict__ s_wt, float* __restrict__ s_red,
    const float* __restrict__ prow, float* __restrict__ crow,
    int t0g, int co0, int r0, int* cnt_g, int wait_target, int tid)
{
    // -- x prefetch: this thread outputs (t_outb, t_outb+32) x co-pair cp2; own-slice only --
    const int cp2    = tid & 7;
    const int t_outb = tid >> 3;       // 0..31
    float* outp0 = crow + (size_t)(t0g + t_outb) * Cc + co0 + cp2 * 2;
    float* outp1 = outp0 + 32 * Cc;
    float2 xv0 = *(const float2*)outp0;
    float2 xv1 = *(const float2*)outp1;

    // -- warp-level spin: wait for peer blocks of this batch --
    if ((tid & 31) == 0) {
        int v;
        do {
            asm volatile("ld.acquire.gpu.global.s32 %0, [%1];" : "=r"(v) : "l"(cnt_g));
        } while (v < wait_target);
    }
    __syncwarp();

    // -- fill s_prev: 68 in-range rows (pads are pre-zeroed, static) --
    // NOTE: CP=130 -> odd rows are only 8B-aligned; store as 2x float2 (not float4)
    {
        const int t_base = t0g - PWPAD + r0;
#pragma unroll
        for (int it = 0; it < (FILL_ROWS * 32) / NTHR; ++it) {
            int idx = tid + it * NTHR;
            int row_rel = idx >> 5;
            int chunk = idx & 31;
            float4 v = __ldcg((const float4*)(prow + (t_base + row_rel) * Cc + chunk * 4));
            float* d = s_prev + (r0 + row_rel) * CP + chunk * 4;
            *(float2*)(d)     = make_float2(v.x, v.y);
            *(float2*)(d + 2) = make_float2(v.z, v.w);
        }
        // tail: 68*32 = 2176 = 8*256 + 128
        int idx = tid + ((FILL_ROWS * 32) / NTHR) * NTHR;
        if (idx < FILL_ROWS * 32) {
            int row_rel = idx >> 5;
            int chunk = idx & 31;
            float4 v = __ldcg((const float4*)(prow + (t_base + row_rel) * Cc + chunk * 4));
            float* d = s_prev + (r0 + row_rel) * CP + chunk * 4;
            *(float2*)(d)     = make_float2(v.x, v.y);
            *(float2*)(d + 2) = make_float2(v.z, v.w);
        }
    }
    __syncthreads();

    // -- compute --
    const int cg  = tid & 15;
    const int tg  = (tid >> 4) & 7;
    const int cop = tid >> 7;
    const int tl0 = tg * 8;

    unsigned long long acc[8][4];
#pragma unroll
    for (int j = 0; j < 8; ++j)
#pragma unroll
        for (int cp = 0; cp < 4; ++cp) acc[j][cp] = 0ull;

    for (int i = 0; i < 8; ++i) {
        const int ci = cg + 16 * i;
        unsigned long long a2[16];
#pragma unroll
        for (int j = 0; j < 16; ++j) {
            unsigned u = __float_as_uint(s_prev[(tl0 + j) * CP + ci]);
            asm("mov.b64 %0, {%1, %1};" : "=l"(a2[j]) : "r"(u));
        }
#pragma unroll
        for (int k = 0; k < KWIN; ++k) {
            const float* wr = &s_wt[(k * Cc + ci) * WPITCH + cop * 8];
#pragma unroll
            for (int cp = 0; cp < 4; ++cp) {
                unsigned long long w2 = *(const unsigned long long*)(wr + 2 * cp);
#pragma unroll
                for (int j = 0; j < 8; ++j) {
                    asm("fma.rn.f32x2 %0, %1, %2, %0;"
                        : "+l"(acc[j][cp]) : "l"(a2[j + k]), "l"(w2));
                }
            }
        }
    }

    // -- stash partials (separate region: no pre-barrier needed) --
    float* myred = s_red + cop * COPSTRIDE + (tg * 16 + cg) * REDP;
#pragma unroll
    for (int j = 0; j < 8; ++j)
#pragma unroll
        for (int cp = 0; cp < 4; ++cp)
            *(unsigned long long*)(myred + j * 8 + 2 * cp) = acc[j][cp];
    __syncthreads();

    // -- 16-way reduce + relu + add x + store (2 outputs per thread) --
#pragma unroll
    for (int half = 0; half < 2; ++half) {
        const int t_o = t_outb + 32 * half;
        const int cop_r = cp2 >> 2;
        const int c_off = (cp2 & 3) * 2;
        const int tg_r = t_o >> 3;
        const int j    = t_o & 7;
        const float* pr = s_red + cop_r * COPSTRIDE + (tg_r * 16) * REDP + j * 8 + c_off;
        float sx = 0.f, sy = 0.f;
#pragma unroll
        for (int g = 0; g < 16; ++g) {
            float2 p = *(const float2*)(pr + g * REDP);
            sx += p.x; sy += p.y;
        }
        float2 xv = half ? xv1 : xv0;
        float2 o;
        o.x = xv.x + fmaxf(sx, 0.f);
        o.y = xv.y + fmaxf(sy, 0.f);
        *(float2*)(half ? outp1 : outp0) = o;
    }

    __syncthreads();
    // release-increment publishes this CTA's stores to the acquire-pollers
    if (tid == 0) {
        asm volatile("red.release.gpu.global.add.s32 [%0], 1;" :: "l"(cnt_g) : "memory");
    }
}

// Persistent kernel: forward scan with Kf, then backward scan with Kb (in-place).
__global__ void __launch_bounds__(NTHR, 1) scan_pair_kernel(
    const float* __restrict__ Kf, const float* __restrict__ Kb,
    float* __restrict__ buf, int* cnt)
{
    extern __shared__ float sm[];
    float* s_prev = sm;
    float* s_wt   = sm + SPREV_FLOATS;
    float* s_red  = sm + SPREV_FLOATS + SWT_FLOATS;

    const int tid   = threadIdx.x;
    const int blk   = blockIdx.x;
    const int b     = blk >> 4;
    const int slice = blk & 15;
    const int t0g   = (slice & 1) * THALF;
    const int co0   = (slice >> 1) * 16;
    const int r0    = (t0g == 0) ? PWPAD : 0;   // first in-range window row

    float* bbase = buf + (size_t)b * Ss * Tt * Cc;
    int* cnt_g = cnt + b;

    // zero the 4 static pad rows of s_prev once
    {
        int pad_start = (t0g == 0) ? 0 : FILL_ROWS;   // rows [pad_start, pad_start+4)
        for (int idx = tid; idx < PWPAD * Cc; idx += NTHR) {
            int r = idx >> 7, c = idx & 127;
            s_prev[(pad_start + r) * CP + c] = 0.f;
        }
    }

    // load forward weights once: s_wt[(k*Cc+ci)*WPITCH + c] = Kf[(k*Cc+ci)*Cc + co0 + c]
    for (int idx = tid; idx < KWIN * Cc * 16; idx += NTHR) {
        int kc = idx >> 4, c = idx & 15;
        s_wt[kc * WPITCH + c] = Kf[(size_t)kc * Cc + co0 + c];
    }
    __syncthreads();

    // forward scan: s = 1..127, prev = s-1
    for (int s = 1; s < Ss; ++s) {
        scan_step(s_prev, s_wt, s_red,
                  bbase + (size_t)(s - 1) * Tt * Cc,
                  bbase + (size_t)s * Tt * Cc,
                  t0g, co0, r0, cnt_g, 16 * (s - 1), tid);
    }

    // switch to backward weights (smem private to block; peers may lag safely)
    __syncthreads();
    for (int idx = tid; idx < KWIN * Cc * 16; idx += NTHR) {
        int kc = idx >> 4, c = idx & 15;
        s_wt[kc * WPITCH + c] = Kb[(size_t)kc * Cc + co0 + c];
    }
    __syncthreads();

    // backward scan: d = 1..127, cur = 127-d, prev = 128-d
    for (int d = 1; d < Ss; ++d) {
        scan_step(s_prev, s_wt, s_red,
                  bbase + (size_t)(Ss - d) * Tt * Cc,
                  bbase + (size_t)(Ss - 1 - d) * Tt * Cc,
                  t0g, co0, r0, cnt_g, 16 * (126 + d), tid);
    }
}

// ---------------------------------------------------------------------------
extern "C" void kernel_launch(void* const* d_in, const int* in_sizes, int n_in,
                              void* d_out, int out_size) {
    const float* x    = (const float*)d_in[0];
    const float* k_td = (const float*)d_in[1];
    const float* k_dt = (const float*)d_in[2];
    const float* k_lr = (const float*)d_in[3];
    const float* k_rl = (const float*)d_in[4];
    float* out = (float*)d_out;

    float *b0, *b1;
    int *c0, *c1;
    cudaGetSymbolAddress((void**)&b0, g_buf0);
    cudaGetSymbolAddress((void**)&b1, g_buf1);
    cudaGetSymbolAddress((void**)&c0, g_cnt0);
    cudaGetSymbolAddress((void**)&c1, g_cnt1);

    cudaFuncSetAttribute(scan_pair_kernel, cudaFuncAttributeMaxDynamicSharedMemorySize, SMEM_BYTES);

    dim3 tgrid(Ww / 32, Cc / 32, Bx * Hh);
    dim3 tblk(32, 8);

    reset_kernel<<<1, 32>>>(c0, c1);

    // (B,C,H,W) -> (B,H,W,C)
    transpose_in_kernel<<<tgrid, tblk>>>(x, b0);

    // vertical scans (td then dt), persistent
    scan_pair_kernel<<<128, NTHR, SMEM_BYTES>>>(k_td, k_dt, b0, c0);

    // (B,H,W,C) -> (B,W,H,C)
    transpose_mid_kernel<<<Bx * Ss, 128>>>(b0, b1);

    // horizontal scans (lr then rl), persistent
    scan_pair_kernel<<<128, NTHR, SMEM_BYTES>>>(k_lr, k_rl, b1, c1);

    // (B,W,H,C) -> (B,C,H,W)
    transpose_out_kernel<<<tgrid, tblk>>>(b1, out);
}

// round 14
// speedup vs baseline: 1.8459x; 1.0093x over previous
#include <cuda_runtime.h>
#include <cstdint>

// Problem constants
#define Bx 8
#define Cc 128
#define Hh 128
#define Ww 128
#define KWIN 9
#define PWPAD 4
#define Tt 128   // conv (row) dimension
#define Ss 128   // scan dimension

// Block decomposition: 128 blocks = 8 batches x (2 T-halves x 8 co-tiles of 16)
#define THALF 64
#define WIN_ROWS (THALF + 2*PWPAD)       // 72
#define FILL_ROWS 68                      // in-range rows per step (4 pad rows static)
#define NTHR 256

// smem layout (floats)
#define CP 130                            // s_prev pitch: 8-row offset = 16 banks -> conflict-free
#define SPREV_FLOATS (WIN_ROWS * CP)      // 9360
#define WPITCH 18                         // s_wt per-(k,ci) pitch: 18*cg distinct mod 32
#define SWT_FLOATS (KWIN * Cc * WPITCH)   // 20736
#define REDP 66                           // stash pitch: 64 floats payload + 2 pad (even, 2cg banks)
#define COPSTRIDE (128 * REDP + 16)       // 8464: +16 banks separates cop halves for reduce
#define SRED_FLOATS (2 * COPSTRIDE)       // 16928
#define SMEM_BYTES ((SPREV_FLOATS + SWT_FLOATS + SRED_FLOATS) * 4)  // 188096 B

// Scratch tensors (B, S, T, C)
__device__ float g_buf0[(size_t)Bx*Ss*Tt*Cc];
__device__ float g_buf1[(size_t)Bx*Ss*Tt*Cc];
// Per-batch sync counters (one set per scan kernel)
__device__ int g_cnt0[Bx];
__device__ int g_cnt1[Bx];

// ---------------------------------------------------------------------------
__global__ void reset_kernel(int* c0, int* c1) {
    if (threadIdx.x < Bx) { c0[threadIdx.x] = 0; c1[threadIdx.x] = 0; }
}

// transpose_in: x (B,C,H,W) -> buf (B,H,W,C)
__global__ void transpose_in_kernel(const float* __restrict__ x, float* __restrict__ out) {
    __shared__ float tile[32][33];
    int w0 = blockIdx.x * 32, c0 = blockIdx.y * 32;
    int bh = blockIdx.z;
    int b = bh >> 7, h = bh & 127;
#pragma unroll
    for (int j = 0; j < 32; j += 8) {
        int c = c0 + threadIdx.y + j;
        tile[threadIdx.y + j][threadIdx.x] =
            x[((size_t)(b * Cc + c) * Hh + h) * Ww + w0 + threadIdx.x];
    }
    __syncthreads();
#pragma unroll
    for (int j = 0; j < 32; j += 8) {
        int w = w0 + threadIdx.y + j;
        out[((size_t)(b * Hh + h) * Ww + w) * Cc + c0 + threadIdx.x] =
            tile[threadIdx.x][threadIdx.y + j];
    }
}

// transpose_mid: (B,S,T,C) -> (B,T,S,C)
__global__ void transpose_mid_kernel(const float* __restrict__ in, float* __restrict__ out) {
    int bs = blockIdx.x;
    int b = bs >> 7, s = bs & 127;
    int tid = threadIdx.x;
    int toff = tid >> 5;
    int c4 = (tid & 31) * 4;
    for (int tb = 0; tb < Tt; tb += 4) {
        int t = tb + toff;
        float4 v = *(const float4*)(in + ((size_t)((b * Ss + s) * Tt + t)) * Cc + c4);
        *(float4*)(out + ((size_t)((b * Tt + t) * Ss + s)) * Cc + c4) = v;
    }
}

// transpose_out: buf1 (B, W, H, C) -> out (B, C, H, W)
__global__ void transpose_out_kernel(const float* __restrict__ in, float* __restrict__ out) {
    __shared__ float tile[32][33];
    int w0 = blockIdx.x * 32, c0 = blockIdx.y * 32;
    int bh = blockIdx.z;
    int b = bh >> 7, h = bh & 127;
#pragma unroll
    for (int j = 0; j < 32; j += 8) {
        int w = w0 + threadIdx.y + j;
        tile[threadIdx.y + j][threadIdx.x] =
            in[((size_t)(b * Ww + w) * Hh + h) * Cc + c0 + threadIdx.x];
    }
    __syncthreads();
#pragma unroll
    for (int j = 0; j < 32; j += 8) {
        int c = c0 + threadIdx.y + j;
        out[((size_t)(b * Cc + c) * Hh + h) * Ww + w0 + threadIdx.x] =
            tile[threadIdx.x][threadIdx.y + j];
    }
}

// ---------------------------------------------------------------------------
// One scan step: crow[t, co] += relu( sum_{k,ci} prow[t+k-4, ci] * W[k, ci, co] )
// Thread decomp (256): tid = cop(2)*128 + tg(8)*16 + cg(16)
//   thread tile: 8 t (tg*8+j) x 8 co (cop*8, 4 pairs), 16-way ci split (cg)
__device__ __forceinline__ void scan_step(
    float* __restrict__ s_prev, const float* __restrict__ s_wt, float* __restrict__ s_red,
    const float* __restrict__ prow, float* __restrict__ crow,
    int t0g, int co0, int r0, int* cnt_g, int wait_target, int tid)
{
    // -- x prefetch: this thread outputs (t_outb, t_outb+32) x co-pair cp2; own-slice only --
    const int cp2    = tid & 7;
    const int t_outb = tid >> 3;       // 0..31
    float* outp0 = crow + (size_t)(t0g + t_outb) * Cc + co0 + cp2 * 2;
    float* outp1 = outp0 + 32 * Cc;
    float2 xv0 = *(const float2*)outp0;
    float2 xv1 = *(const float2*)outp1;

    // -- warp-level spin: wait for peer blocks of this batch --
    if ((tid & 31) == 0) {
        int v;
        do {
            asm volatile("ld.acquire.gpu.global.s32 %0, [%1];" : "=r"(v) : "l"(cnt_g));
        } while (v < wait_target);
    }
    __syncwarp();

    // -- fill s_prev: 68 in-range rows (pads are pre-zeroed, static) --
    // NOTE: CP=130 -> odd rows are only 8B-aligned; store as 2x float2 (not float4)
    {
        const int t_base = t0g - PWPAD + r0;
#pragma unroll
        for (int it = 0; it < (FILL_ROWS * 32) / NTHR; ++it) {
            int idx = tid + it * NTHR;
            int row_rel = idx >> 5;
            int chunk = idx & 31;
            float4 v = __ldcg((const float4*)(prow + (t_base + row_rel) * Cc + chunk * 4));
            float* d = s_prev + (r0 + row_rel) * CP + chunk * 4;
            *(float2*)(d)     = make_float2(v.x, v.y);
            *(float2*)(d + 2) = make_float2(v.z, v.w);
        }
        // tail: 68*32 = 2176 = 8*256 + 128
        int idx = tid + ((FILL_ROWS * 32) / NTHR) * NTHR;
        if (idx < FILL_ROWS * 32) {
            int row_rel = idx >> 5;
            int chunk = idx & 31;
            float4 v = __ldcg((const float4*)(prow + (t_base + row_rel) * Cc + chunk * 4));
            float* d = s_prev + (r0 + row_rel) * CP + chunk * 4;
            *(float2*)(d)     = make_float2(v.x, v.y);
            *(float2*)(d + 2) = make_float2(v.z, v.w);
        }
    }
    __syncthreads();

    // -- compute --
    const int cg  = tid & 15;
    const int tg  = (tid >> 4) & 7;
    const int cop = tid >> 7;
    const int tl0 = tg * 8;

    unsigned long long acc[8][4];
#pragma unroll
    for (int j = 0; j < 8; ++j)
#pragma unroll
        for (int cp = 0; cp < 4; ++cp) acc[j][cp] = 0ull;

    for (int i = 0; i < 8; ++i) {
        const int ci = cg + 16 * i;
        unsigned long long a2[16];
#pragma unroll
        for (int j = 0; j < 16; ++j) {
            unsigned u = __float_as_uint(s_prev[(tl0 + j) * CP + ci]);
            asm("mov.b64 %0, {%1, %1};" : "=l"(a2[j]) : "r"(u));
        }
#pragma unroll
        for (int k = 0; k < KWIN; ++k) {
            const float* wr = &s_wt[(k * Cc + ci) * WPITCH + cop * 8];
#pragma unroll
            for (int cp = 0; cp < 4; ++cp) {
                unsigned long long w2 = *(const unsigned long long*)(wr + 2 * cp);
#pragma unroll
                for (int j = 0; j < 8; ++j) {
                    asm("fma.rn.f32x2 %0, %1, %2, %0;"
                        : "+l"(acc[j][cp]) : "l"(a2[j + k]), "l"(w2));
                }
            }
        }
    }

    // -- stash partials (separate region: no pre-barrier needed) --
    float* myred = s_red + cop * COPSTRIDE + (tg * 16 + cg) * REDP;
#pragma unroll
    for (int j = 0; j < 8; ++j)
#pragma unroll
        for (int cp = 0; cp < 4; ++cp)
            *(unsigned long long*)(myred + j * 8 + 2 * cp) = acc[j][cp];
    __syncthreads();

    // -- 16-way reduce + relu + add x + store (2 outputs per thread) --
#pragma unroll
    for (int half = 0; half < 2; ++half) {
        const int t_o = t_outb + 32 * half;
        const int cop_r = cp2 >> 2;
        const int c_off = (cp2 & 3) * 2;
        const int tg_r = t_o >> 3;
        const int j    = t_o & 7;
        const float* pr = s_red + cop_r * COPSTRIDE + (tg_r * 16) * REDP + j * 8 + c_off;
        float sx = 0.f, sy = 0.f;
#pragma unroll
        for (int g = 0; g < 16; ++g) {
            float2 p = *(const float2*)(pr + g * REDP);
            sx += p.x; sy += p.y;
        }
        float2 xv = half ? xv1 : xv0;
        float2 o;
        o.x = xv.x + fmaxf(sx, 0.f);
        o.y = xv.y + fmaxf(sy, 0.f);
        *(float2*)(half ? outp1 : outp0) = o;
    }

    __syncthreads();
    // release-increment publishes this CTA's stores to the acquire-pollers
    if (tid == 0) {
        asm volatile("red.release.gpu.global.add.s32 [%0], 1;" :: "l"(cnt_g) : "memory");
    }
}

// Persistent kernel: forward scan with Kf, then backward scan with Kb (in-place).
__global__ void __launch_bounds__(NTHR, 1) scan_pair_kernel(
    const float* __restrict__ Kf, const float* __restrict__ Kb,
    float* __restrict__ buf, int* cnt)
{
    extern __shared__ float sm[];
    float* s_prev = sm;
    float* s_wt   = sm + SPREV_FLOATS;
    float* s_red  = sm + SPREV_FLOATS + SWT_FLOATS;

    const int tid   = threadIdx.x;
    const int blk   = blockIdx.x;
    const int b     = blk >> 4;
    const int slice = blk & 15;
    const int t0g   = (slice & 1) * THALF;
    const int co0   = (slice >> 1) * 16;
    const int r0    = (t0g == 0) ? PWPAD : 0;   // first in-range window row

    float* bbase = buf + (size_t)b * Ss * Tt * Cc;
    int* cnt_g = cnt + b;

    // zero the 4 static pad rows of s_prev once
    {
        int pad_start = (t0g == 0) ? 0 : FILL_ROWS;   // rows [pad_start, pad_start+4)
        for (int idx = tid; idx < PWPAD * Cc; idx += NTHR) {
            int r = idx >> 7, c = idx & 127;
            s_prev[(pad_start + r) * CP + c] = 0.f;
        }
    }

    // load forward weights once: s_wt[(k*Cc+ci)*WPITCH + c] = Kf[(k*Cc+ci)*Cc + co0 + c]
    for (int idx = tid; idx < KWIN * Cc * 16; idx += NTHR) {
        int kc = idx >> 4, c = idx & 15;
        s_wt[kc * WPITCH + c] = Kf[(size_t)kc * Cc + co0 + c];
    }
    __syncthreads();

    // forward scan: s = 1..127, prev = s-1
    for (int s = 1; s < Ss; ++s) {
        scan_step(s_prev, s_wt, s_red,
                  bbase + (size_t)(s - 1) * Tt * Cc,
                  bbase + (size_t)s * Tt * Cc,
                  t0g, co0, r0, cnt_g, 16 * (s - 1), tid);
    }

    // switch to backward weights (smem private to block; peers may lag safely)
    __syncthreads();
    for (int idx = tid; idx < KWIN * Cc * 16; idx += NTHR) {
        int kc = idx >> 4, c = idx & 15;
        s_wt[kc * WPITCH + c] = Kb[(size_t)kc * Cc + co0 + c];
    }
    __syncthreads();

    // backward scan: d = 1..127, cur = 127-d, prev = 128-d
    for (int d = 1; d < Ss; ++d) {
        scan_step(s_prev, s_wt, s_red,
                  bbase + (size_t)(Ss - d) * Tt * Cc,
                  bbase + (size_t)(Ss - 1 - d) * Tt * Cc,
                  t0g, co0, r0, cnt_g, 16 * (126 + d), tid);
    }
}

// ---------------------------------------------------------------------------
extern "C" void kernel_launch(void* const* d_in, const int* in_sizes, int n_in,
                              void* d_out, int out_size) {
    const float* x    = (const float*)d_in[0];
    const float* k_td = (const float*)d_in[1];
    const float* k_dt = (const float*)d_in[2];
    const float* k_lr = (const float*)d_in[3];
    const float* k_rl = (const float*)d_in[4];
    float* out = (float*)d_out;

    float *b0, *b1;
    int *c0, *c1;
    cudaGetSymbolAddress((void**)&b0, g_buf0);
    cudaGetSymbolAddress((void**)&b1, g_buf1);
    cudaGetSymbolAddress((void**)&c0, g_cnt0);
    cudaGetSymbolAddress((void**)&c1, g_cnt1);

    cudaFuncSetAttribute(scan_pair_kernel, cudaFuncAttributeMaxDynamicSharedMemorySize, SMEM_BYTES);

    dim3 tgrid(Ww / 32, Cc / 32, Bx * Hh);
    dim3 tblk(32, 8);

    reset_kernel<<<1, 32>>>(c0, c1);

    // (B,C,H,W) -> (B,H,W,C)
    transpose_in_kernel<<<tgrid, tblk>>>(x, b0);

    // vertical scans (td then dt), persistent
    scan_pair_kernel<<<128, NTHR, SMEM_BYTES>>>(k_td, k_dt, b0, c0);

    // (B,H,W,C) -> (B,W,H,C)
    transpose_mid_kernel<<<Bx * Ss, 128>>>(b0, b1);

    // horizontal scans (lr then rl), persistent
    scan_pair_kernel<<<128, NTHR, SMEM_BYTES>>>(k_lr, k_rl, b1, c1);

    // (B,W,H,C) -> (B,C,H,W)
    transpose_out_kernel<<<tgrid, tblk>>>(b1, out);
}